// round 1
// baseline (speedup 1.0000x reference)
#include <cuda_runtime.h>
#include <cuda_bf16.h>

// dLDS_continuous: out[b] = expm(sum_m c[b,m] * G[m]) @ x[b]
// B = 2097152 batches, N = 3 (3x3 matrices), M = 6 basis operators.
//
// Algorithm per batch (all fp32, registers):
//   1. T = sum_m c[b,m] * G[m]              (G broadcast from shared)
//   2. s = max(0, ilogb-style exponent of ||T||_F)  -> ||T/2^s|| <= 1
//   3. E = Taylor_9(T / 2^s) via Horner      (8 3x3 matmuls)
//   4. E = E^(2^s)                           (s squarings, s typically 2, max ~4)
//   5. out = E @ x
//
// Error budget: Taylor-9 remainder at theta=1 is ~7e-7; squaring amplifies
// by ~2^s (<=32) -> ~2e-5 plus fp32 rounding. Well under the 1e-3 gate.

static constexpr int B_TOTAL = 2097152;
static constexpr int THREADS = 256;

__global__ void __launch_bounds__(THREADS)
expm_apply_kernel(const float* __restrict__ x,
                  const float* __restrict__ c,
                  const float* __restrict__ G,
                  float* __restrict__ out)
{
    __shared__ float sG[54];
    int tid = threadIdx.x;
    if (tid < 54) sG[tid] = G[tid];
    __syncthreads();

    int b = blockIdx.x * blockDim.x + tid;
    if (b >= B_TOTAL) return;

    // ---- load c[b, 0:6] as 3x float2 (24-byte stride keeps 8B alignment) ----
    const float2* c2 = reinterpret_cast<const float2*>(c) + (size_t)b * 3;
    float2 cv0 = c2[0];
    float2 cv1 = c2[1];
    float2 cv2 = c2[2];
    float cc[6] = {cv0.x, cv0.y, cv1.x, cv1.y, cv2.x, cv2.y};

    // ---- T = sum_m c[m] * G[m]  (row-major 3x3 in A[9]) ----
    float A[9];
#pragma unroll
    for (int k = 0; k < 9; ++k) {
        float s = cc[0] * sG[k];
#pragma unroll
        for (int m = 1; m < 6; ++m) s = fmaf(cc[m], sG[m * 9 + k], s);
        A[k] = s;
    }

    // ---- scaling: find s with ||A||_F / 2^s <= 1 ----
    float n2 = 0.f;
#pragma unroll
    for (int k = 0; k < 9; ++k) n2 = fmaf(A[k], A[k], n2);
    float nf = sqrtf(n2);

    // exponent e such that nf < 2^e (frexp convention: nf = m * 2^e, m in [0.5,1))
    int e = 0;
    frexpf(nf, &e);
    int s = e > 0 ? e : 0;
    if (s > 24) s = 24;  // safety clamp (unreachable for sane inputs)

    // exact power-of-two scale: 2^{-s}
    float sc = __int_as_float((127 - s) << 23);
#pragma unroll
    for (int k = 0; k < 9; ++k) A[k] *= sc;

    // ---- Taylor degree 9, Horner:  P = I + A/9; then P = I + (A*P)/k, k=8..1 ----
    float P[9];
#pragma unroll
    for (int k = 0; k < 9; ++k) P[k] = A[k] * (1.0f / 9.0f);
    P[0] += 1.f; P[4] += 1.f; P[8] += 1.f;

    const float rcp[8] = {1.f, 1.f / 2.f, 1.f / 3.f, 1.f / 4.f,
                          1.f / 5.f, 1.f / 6.f, 1.f / 7.f, 1.f / 8.f};
#pragma unroll
    for (int k = 8; k >= 1; --k) {
        float Q[9];
#pragma unroll
        for (int i = 0; i < 3; ++i) {
#pragma unroll
            for (int j = 0; j < 3; ++j) {
                Q[i * 3 + j] = fmaf(A[i * 3 + 0], P[0 + j],
                               fmaf(A[i * 3 + 1], P[3 + j],
                                    A[i * 3 + 2] * P[6 + j]));
            }
        }
        float r = rcp[k - 1];
#pragma unroll
        for (int t = 0; t < 9; ++t) P[t] = Q[t] * r;
        P[0] += 1.f; P[4] += 1.f; P[8] += 1.f;
    }

    // ---- repeated squaring: P <- P^2, s times ----
    for (int it = 0; it < s; ++it) {
        float Q[9];
#pragma unroll
        for (int i = 0; i < 3; ++i) {
#pragma unroll
            for (int j = 0; j < 3; ++j) {
                Q[i * 3 + j] = fmaf(P[i * 3 + 0], P[0 + j],
                               fmaf(P[i * 3 + 1], P[3 + j],
                                    P[i * 3 + 2] * P[6 + j]));
            }
        }
#pragma unroll
        for (int t = 0; t < 9; ++t) P[t] = Q[t];
    }

    // ---- out = P @ x ----
    const float* xb = x + (size_t)b * 3;
    float x0 = xb[0], x1 = xb[1], x2 = xb[2];
    float* ob = out + (size_t)b * 3;
    ob[0] = fmaf(P[0], x0, fmaf(P[1], x1, P[2] * x2));
    ob[1] = fmaf(P[3], x0, fmaf(P[4], x1, P[5] * x2));
    ob[2] = fmaf(P[6], x0, fmaf(P[7], x1, P[8] * x2));
}

extern "C" void kernel_launch(void* const* d_in, const int* in_sizes, int n_in,
                              void* d_out, int out_size)
{
    const float* x = (const float*)d_in[0];   // (B, 3, 1)
    const float* c = (const float*)d_in[1];   // (B, 6)
    const float* G = (const float*)d_in[2];   // (6, 3, 3)
    float* out = (float*)d_out;               // (B, 3, 1)

    int grid = (B_TOTAL + THREADS - 1) / THREADS;
    expm_apply_kernel<<<grid, THREADS>>>(x, c, G, out);
}